// round 12
// baseline (speedup 1.0000x reference)
#include <cuda_runtime.h>
#include <cuda_fp16.h>
#include <cstdint>
#include <math.h>

#define BBATCH 4
#define TT   16
#define PPX  4356          // 66*66 padded pixels
#define GRD  192           // guard pixels at both ends of padded arrays
#define NTOT ((2*GRD + BBATCH*PPX) * 64)
#define XTOT ((2*GRD + BBATCH*TT*PPX) * 32)
#define NC   (BBATCH * PPX * 64)
#define NSTRIP 35
#define ZXN  (BBATCH * TT * NSTRIP * 128 * 256)   // halves

// ---------------- static device state ----------------
__device__ __half g_h[2][NTOT];          // hidden state, single fp16 plane
__device__ float  g_c[NC];
__device__ __half g_x[XTOT];             // padded input, single fp16 plane
__device__ __half g_zx[ZXN];             // precomputed x-conv + bias, fp16
// mma.sync B fragments (single fp16 plane), lane-ordered:
// Wh: [tap(9)][chunk(4)][ntile(32)][lane(32)] -> uint2 {b0,b1}
// Wx: [tap(9)][chunk(2)][ntile(32)][lane(32)]
__device__ uint2 g_WhF[9 * 4 * 32 * 32];
__device__ uint2 g_WxF[9 * 2 * 32 * 32];

// ---------------- helpers ----------------
__device__ __forceinline__ uint32_t smem_u32(const void* p) {
    uint32_t a;
    asm("{ .reg .u64 t; cvta.to.shared.u64 t, %1; cvt.u32.u64 %0, t; }" : "=r"(a) : "l"(p));
    return a;
}

#define LDMX4(r, addr) \
    asm volatile("ldmatrix.sync.aligned.m8n8.x4.shared.b16 {%0,%1,%2,%3}, [%4];" \
        : "=r"((r)[0]), "=r"((r)[1]), "=r"((r)[2]), "=r"((r)[3]) : "r"(addr))

#define MMA_FP16(d, a, bf) \
    asm volatile("mma.sync.aligned.m16n8k16.row.col.f32.f16.f16.f32 " \
        "{%0,%1,%2,%3}, {%4,%5,%6,%7}, {%8,%9}, {%0,%1,%2,%3};" \
        : "+f"((d)[0]), "+f"((d)[1]), "+f"((d)[2]), "+f"((d)[3]) \
        : "r"((a)[0]), "r"((a)[1]), "r"((a)[2]), "r"((a)[3]), "r"((bf).x), "r"((bf).y))

__device__ __forceinline__ uint32_t enc_h(float v) {
    return (uint32_t)__half_as_ushort(__float2half_rn(v));
}

// ---------------- prep kernels ----------------
__global__ void zero_kernel() {
    int i = blockIdx.x * blockDim.x + threadIdx.x;
    if (i < NTOT) { g_h[0][i] = __float2half(0.f); g_h[1][i] = __float2half(0.f); }
    if (i < NC) g_c[i] = 0.f;
}

__global__ void pad_x_kernel(const float* __restrict__ x) {
    long i = (long)blockIdx.x * blockDim.x + threadIdx.x;
    if (i >= XTOT) return;
    int ci = (int)(i & 31);
    long p = i >> 5;
    float v = 0.f;
    if (p >= GRD && p < GRD + (long)BBATCH * TT * PPX) {
        long pp = p - GRD;
        int bt = (int)(pp / PPX), q = (int)(pp % PPX);
        int py = q / 66, px = q % 66;
        if (py >= 1 && py <= 64 && px >= 1 && px <= 64)
            v = x[(((long)bt * 4096) + (py - 1) * 64 + (px - 1)) * 32 + ci];
    }
    g_x[i] = __float2half_rn(v);
}

__global__ void prep_w_kernel(const float* __restrict__ Wx, const float* __restrict__ Wh) {
    int idx = blockIdx.x * blockDim.x + threadIdx.x;
    if (idx < 36864) {                    // Wh fragments: tap(9) x chunk(4)
        int tap   = idx >> 12;
        int r     = idx & 4095;
        int chunk = r >> 10;
        int r3    = r & 1023;
        int nt    = r3 >> 5, lane = r3 & 31;
        int k0 = chunk * 16 + (lane & 3) * 2;
        int n  = nt * 8 + (lane >> 2);
        float v00 = Wh[((size_t)tap * 64 + k0    ) * 256 + n];
        float v01 = Wh[((size_t)tap * 64 + k0 + 1) * 256 + n];
        float v10 = Wh[((size_t)tap * 64 + k0 + 8) * 256 + n];
        float v11 = Wh[((size_t)tap * 64 + k0 + 9) * 256 + n];
        uint2 o;
        o.x = enc_h(v00) | (enc_h(v01) << 16);
        o.y = enc_h(v10) | (enc_h(v11) << 16);
        g_WhF[idx] = o;
    } else if (idx < 36864 + 18432) {     // Wx fragments: tap(9) x chunk(2)
        int j     = idx - 36864;
        int tap   = j >> 11;
        int r     = j & 2047;
        int chunk = r >> 10;
        int r3    = r & 1023;
        int nt    = r3 >> 5, lane = r3 & 31;
        int k0 = chunk * 16 + (lane & 3) * 2;
        int n  = nt * 8 + (lane >> 2);
        float v00 = Wx[((size_t)tap * 32 + k0    ) * 256 + n];
        float v01 = Wx[((size_t)tap * 32 + k0 + 1) * 256 + n];
        float v10 = Wx[((size_t)tap * 32 + k0 + 8) * 256 + n];
        float v11 = Wx[((size_t)tap * 32 + k0 + 9) * 256 + n];
        uint2 o;
        o.x = enc_h(v00) | (enc_h(v01) << 16);
        o.y = enc_h(v10) | (enc_h(v11) << 16);
        g_WxF[j] = o;
    }
}

// ---------------- xconv: zx = conv3x3(x, Wx) + bias, fp16 out, all frames ---
// smem: phase 1: x slab 262 rows x 80B = 20960 (aliases z region)
//       phase 2: z16[128][264] halves = 67584
//       bias[256] fp32 at 67584
#define XC_BIAS  67584
#define XC_SMEM  68608

__global__ void __launch_bounds__(512, 1)
xconv_kernel(const float* __restrict__ bias)
{
    extern __shared__ __align__(16) char smem[];
    float* bsx = (float*)(smem + XC_BIAS);

    const int tid  = threadIdx.x;
    const int lane = tid & 31;
    const int wid  = tid >> 5;
    const int wm   = wid & 1;
    const int wn   = wid >> 1;
    const int bt   = blockIdx.y;
    const int q0   = blockIdx.x * 128;

    if (tid < 256) bsx[tid] = bias[tid];

    // ---- load x slab (padded rows q0-67 .. q0+194) ----
    {
        long offx = (long)GRD * 32 + ((long)bt * PPX + q0 - 67) * 32;
        const uint4* xh = (const uint4*)(g_x + offx);
        for (int i = tid; i < 1048; i += 512) {
            int r = i >> 2, c = i & 3;
            *(uint4*)(smem + r * 80 + c * 16) = xh[i];
        }
    }
    __syncthreads();

    float acc[4][4][4];
#pragma unroll
    for (int mt = 0; mt < 4; ++mt)
#pragma unroll
        for (int nt = 0; nt < 4; ++nt)
#pragma unroll
            for (int e = 0; e < 4; ++e) acc[mt][nt][e] = 0.f;

    const uint32_t sx_u = smem_u32(smem);
    const int rowA = lane & 15;
    const int colh = (lane >> 4) * 16;

    for (int tap = 0; tap < 9; ++tap) {
        const int shift = (tap / 3) * 66 + (tap % 3);
        const uint32_t a_base = sx_u + (uint32_t)(shift + wm * 64 + rowA) * 80 + colh;
#pragma unroll
        for (int chunk = 0; chunk < 2; ++chunk) {
            const uint2* ph = g_WxF + (size_t)(tap * 2 + chunk) * 1024 + wn * 128 + lane;
            uint2 bh[4];
#pragma unroll
            for (int nt = 0; nt < 4; ++nt) bh[nt] = ph[nt * 32];
#pragma unroll
            for (int mt = 0; mt < 4; ++mt) {
                uint32_t ah[4];
                LDMX4(ah, a_base + mt * (16 * 80) + chunk * 32);
#pragma unroll
                for (int nt = 0; nt < 4; ++nt) MMA_FP16(acc[mt][nt], ah, bh[nt]);
            }
        }
    }

    __syncthreads();   // done reading slab; z16 aliases it

    // ---- scatter z (+bias) to smem as fp16, stride 264 halves ----
#pragma unroll
    for (int mt = 0; mt < 4; ++mt)
#pragma unroll
        for (int nt = 0; nt < 4; ++nt) {
            int px = wm * 64 + mt * 16 + (lane >> 2);
            int n  = wn * 32 + nt * 8 + (lane & 3) * 2;
            float b0 = bsx[n], b1 = bsx[n + 1];
            *(__half2*)(smem + px * 528 + n * 2) =
                __floats2half2_rn(acc[mt][nt][0] + b0, acc[mt][nt][1] + b1);
            *(__half2*)(smem + (px + 8) * 528 + n * 2) =
                __floats2half2_rn(acc[mt][nt][2] + b0, acc[mt][nt][3] + b1);
        }
    __syncthreads();

    // ---- coalesced fp16 store to gmem (64KB per CTA) ----
    uint32_t* dst = (uint32_t*)(g_zx + ((size_t)bt * NSTRIP + blockIdx.x) * 32768);
    for (int i = tid; i < 16384; i += 512) {
        int row = i >> 7, c = i & 127;
        dst[i] = *(const uint32_t*)(smem + row * 528 + c * 4);
    }
}

// ---------------- fused ConvLSTM step (h-conv only, mma.sync fp16) ----------
// smem layout (bytes):
//   phase 1 (conv):   [0      : 37728) h slab  262 rows x 144B
//   phase 2 (epilog): [0      :133120) z[128][260] fp32  (aliases slab)
//   always:           [133120 :141312) Wp[32][64] fp32
//                     [141312 :141568) bp[64] fp32
#define SM_WP    133120
#define SM_BP    141312
#define SM_TOTAL 141568

__global__ void __launch_bounds__(512, 1)
step_kernel(const float* __restrict__ Wp, const float* __restrict__ bp,
            const float* __restrict__ xin, float* __restrict__ out, int t)
{
    extern __shared__ __align__(16) char smem[];
    float* zs   = (float*)smem;
    float* wp_s = (float*)(smem + SM_WP);
    float* bp_s = (float*)(smem + SM_BP);

    const int tid  = threadIdx.x;
    const int lane = tid & 31;
    const int wid  = tid >> 5;
    const int wm   = wid & 1;
    const int wn   = wid >> 1;
    const int b    = blockIdx.y;
    const int q0   = blockIdx.x * 128;
    const int bt   = b * TT + t;

    for (int i = tid; i < 2048; i += 512) wp_s[i] = Wp[i];
    if (tid < 64) bp_s[tid] = bp[tid];

    // ---- load h slab (padded rows q0-67 .. q0+194) ----
    {
        long off = (long)GRD * 64 + ((long)b * PPX + q0 - 67) * 64;
        const uint4* sh = (const uint4*)(g_h[t & 1] + off);
        for (int i = tid; i < 2096; i += 512) {
            int r = i >> 3, c = i & 7;
            *(uint4*)(smem + r * 144 + c * 16) = sh[i];
        }
    }
    __syncthreads();

    float acc[4][4][4];
#pragma unroll
    for (int mt = 0; mt < 4; ++mt)
#pragma unroll
        for (int nt = 0; nt < 4; ++nt)
#pragma unroll
            for (int e = 0; e < 4; ++e) acc[mt][nt][e] = 0.f;

    const uint32_t sh_u = smem_u32(smem);
    const int rowA = lane & 15;
    const int colh = (lane >> 4) * 16;

    // ---- h taps: 9 x (K=64, 4 k16-chunks), single fp16 product ----
    for (int tap = 0; tap < 9; ++tap) {
        const int shift = (tap / 3) * 66 + (tap % 3);
        const uint32_t a_base = sh_u + (uint32_t)(shift + wm * 64 + rowA) * 144 + colh;
#pragma unroll
        for (int chunk = 0; chunk < 4; ++chunk) {
            const uint2* ph = g_WhF + (size_t)(tap * 4 + chunk) * 1024 + wn * 128 + lane;
            uint2 bh[4];
#pragma unroll
            for (int nt = 0; nt < 4; ++nt) bh[nt] = ph[nt * 32];
#pragma unroll
            for (int mt = 0; mt < 4; ++mt) {
                uint32_t ah[4];
                LDMX4(ah, a_base + mt * (16 * 144) + chunk * 32);
#pragma unroll
                for (int nt = 0; nt < 4; ++nt) MMA_FP16(acc[mt][nt], ah, bh[nt]);
            }
        }
    }

    __syncthreads();   // done reading slab; z aliases it

    // ---- scatter z to smem ----
#pragma unroll
    for (int mt = 0; mt < 4; ++mt)
#pragma unroll
        for (int nt = 0; nt < 4; ++nt) {
            int px = wm * 64 + mt * 16 + (lane >> 2);
            int n  = wn * 32 + nt * 8 + (lane & 3) * 2;
            *(float2*)(zs + px * 260 + n)       = make_float2(acc[mt][nt][0], acc[mt][nt][1]);
            *(float2*)(zs + (px + 8) * 260 + n) = make_float2(acc[mt][nt][2], acc[mt][nt][3]);
        }
    __syncthreads();

    // ---- epilogue: zx(fp16,+bias) + gates, c/h update, fused 1x1 residual ----
    const int pxl = tid >> 2;
    const int q   = q0 + pxl;
    const int py  = q / 66, pxc = q % 66;
    const bool inter = (q < PPX) && py >= 1 && py <= 64 && pxc >= 1 && pxc <= 64;
    if (inter) {
        float* cpt = g_c + ((size_t)b * PPX + q) * 64;
        unsigned short* ho = (unsigned short*)(g_h[(t + 1) & 1] + GRD * 64 + ((size_t)b * PPX + q) * 64);
        float* op = out + ((size_t)bt * 4096 + (py - 1) * 64 + (pxc - 1)) * 64;
        const float* zrow  = zs + pxl * 260;
        const __half* zxrow = g_zx + (((size_t)bt * NSTRIP + blockIdx.x) * 128 + pxl) * 256;
        const float* xrow  = xin + ((size_t)bt * 4096 + (py - 1) * 64 + (pxc - 1)) * 32;
        const int f0base = (tid & 3) * 16;

        float4 xr[8];
#pragma unroll
        for (int i = 0; i < 8; ++i) xr[i] = __ldg((const float4*)xrow + i);

#pragma unroll
        for (int j4 = 0; j4 < 4; ++j4) {
            int f0 = f0base + j4 * 4;
            // residual: res = bp + x . Wp[:, f0:f0+4]
            float4 res = *(const float4*)(bp_s + f0);
#pragma unroll
            for (int ci4 = 0; ci4 < 8; ++ci4) {
                const float* xv = &xr[ci4].x;
#pragma unroll
                for (int cc = 0; cc < 4; ++cc) {
                    float4 w = *(const float4*)(wp_s + (ci4 * 4 + cc) * 64 + f0);
                    float xs = xv[cc];
                    res.x = fmaf(xs, w.x, res.x);
                    res.y = fmaf(xs, w.y, res.y);
                    res.z = fmaf(xs, w.z, res.z);
                    res.w = fmaf(xs, w.w, res.w);
                }
            }

            float4 zi = *(const float4*)(zrow + f0);
            float4 zf = *(const float4*)(zrow + 64 + f0);
            float4 zc = *(const float4*)(zrow + 128 + f0);
            float4 zo = *(const float4*)(zrow + 192 + f0);

            // zx fp16 loads (bias already folded in)
            uint2 uxi = __ldg((const uint2*)(zxrow + f0));
            uint2 uxf = __ldg((const uint2*)(zxrow + 64 + f0));
            uint2 uxc = __ldg((const uint2*)(zxrow + 128 + f0));
            uint2 uxo = __ldg((const uint2*)(zxrow + 192 + f0));
            float2 xi0 = __half22float2(*(__half2*)&uxi.x), xi1 = __half22float2(*(__half2*)&uxi.y);
            float2 xf0 = __half22float2(*(__half2*)&uxf.x), xf1 = __half22float2(*(__half2*)&uxf.y);
            float2 xc0 = __half22float2(*(__half2*)&uxc.x), xc1 = __half22float2(*(__half2*)&uxc.y);
            float2 xo0 = __half22float2(*(__half2*)&uxo.x), xo1 = __half22float2(*(__half2*)&uxo.y);
            float xiv[4] = {xi0.x, xi0.y, xi1.x, xi1.y};
            float xfv[4] = {xf0.x, xf0.y, xf1.x, xf1.y};
            float xcv[4] = {xc0.x, xc0.y, xc1.x, xc1.y};
            float xov[4] = {xo0.x, xo0.y, xo1.x, xo1.y};

            float4 c4 = *(float4*)(cpt + f0);
            float4 o4;
            unsigned short hh[4];
#pragma unroll
            for (int e = 0; e < 4; ++e) {
                float vi = (&zi.x)[e] + xiv[e];
                float vf = (&zf.x)[e] + xfv[e];
                float vc = (&zc.x)[e] + xcv[e];
                float vo = (&zo.x)[e] + xov[e];
                float ig = __saturatef(fmaf(0.2f, vi, 0.5f));
                float fg = __saturatef(fmaf(0.2f, vf, 0.5f));
                float og = __saturatef(fmaf(0.2f, vo, 0.5f));
                float cn = fmaf(fg, (&c4.x)[e], ig * tanhf(vc));
                (&c4.x)[e] = cn;
                float hv = og * tanhf(cn);
                (&o4.x)[e] = hv + (&res.x)[e];
                hh[e] = __half_as_ushort(__float2half_rn(hv));
            }
            *(float4*)(cpt + f0) = c4;
            *(float4*)(op + f0)  = o4;
            uint2 phv = make_uint2((uint32_t)hh[0] | ((uint32_t)hh[1] << 16),
                                   (uint32_t)hh[2] | ((uint32_t)hh[3] << 16));
            *(uint2*)(ho + f0) = phv;
        }
    }
}

// ---------------------------------------------------------------------------
extern "C" void kernel_launch(void* const* d_in, const int* in_sizes, int n_in,
                              void* d_out, int out_size)
{
    const float* x  = (const float*)d_in[0];
    const float* Wx = (const float*)d_in[1];
    const float* Wh = (const float*)d_in[2];
    const float* b  = (const float*)d_in[3];
    const float* Wp = (const float*)d_in[4];
    const float* bp = (const float*)d_in[5];
    float* out = (float*)d_out;

    cudaFuncSetAttribute(step_kernel,
                         cudaFuncAttributeMaxDynamicSharedMemorySize, SM_TOTAL);
    cudaFuncSetAttribute(xconv_kernel,
                         cudaFuncAttributeMaxDynamicSharedMemorySize, XC_SMEM);

    zero_kernel<<<(NTOT + 255) / 256, 256>>>();
    pad_x_kernel<<<(int)((XTOT + 255) / 256), 256>>>(x);
    prep_w_kernel<<<(36864 + 18432 + 255) / 256, 256>>>(Wx, Wh);

    dim3 xgrid(NSTRIP, BBATCH * TT);
    xconv_kernel<<<xgrid, 512, XC_SMEM>>>(b);

    dim3 grid(NSTRIP, BBATCH);
    for (int t = 0; t < TT; ++t)
        step_kernel<<<grid, 512, SM_TOTAL>>>(Wp, bp, x, out, t);
}

// round 13
// speedup vs baseline: 1.5422x; 1.5422x over previous
#include <cuda_runtime.h>
#include <cuda_fp16.h>
#include <cstdint>
#include <math.h>

#define BBATCH 4
#define TT   16
#define PPX  4356          // 66*66 padded pixels
#define GRD  192           // guard pixels at both ends of padded arrays
#define NTOT ((2*GRD + BBATCH*PPX) * 64)
#define XTOT ((2*GRD + BBATCH*TT*PPX) * 32)
#define NC   (BBATCH * PPX * 64)
#define NSTRIP 70          // 64-pixel strips
#define ZXN  (BBATCH * TT * NSTRIP * 64 * 256)   // halves

// ---------------- static device state ----------------
__device__ __half g_h[2][NTOT];          // hidden state, single fp16 plane
__device__ float  g_c[NC];
__device__ __half g_x[XTOT];             // padded input, single fp16 plane
__device__ __half g_zx[ZXN];             // precomputed x-conv + bias, fp16
// mma.sync B fragments (single fp16 plane), lane-ordered:
// Wh: [tap(9)][chunk(4)][ntile(32)][lane(32)] -> uint2 {b0,b1}
// Wx: [tap(9)][chunk(2)][ntile(32)][lane(32)]
__device__ uint2 g_WhF[9 * 4 * 32 * 32];
__device__ uint2 g_WxF[9 * 2 * 32 * 32];

// ---------------- helpers ----------------
__device__ __forceinline__ uint32_t smem_u32(const void* p) {
    uint32_t a;
    asm("{ .reg .u64 t; cvta.to.shared.u64 t, %1; cvt.u32.u64 %0, t; }" : "=r"(a) : "l"(p));
    return a;
}

#define LDMX4(r, addr) \
    asm volatile("ldmatrix.sync.aligned.m8n8.x4.shared.b16 {%0,%1,%2,%3}, [%4];" \
        : "=r"((r)[0]), "=r"((r)[1]), "=r"((r)[2]), "=r"((r)[3]) : "r"(addr))

#define MMA_FP16(d, a, bf) \
    asm volatile("mma.sync.aligned.m16n8k16.row.col.f32.f16.f16.f32 " \
        "{%0,%1,%2,%3}, {%4,%5,%6,%7}, {%8,%9}, {%0,%1,%2,%3};" \
        : "+f"((d)[0]), "+f"((d)[1]), "+f"((d)[2]), "+f"((d)[3]) \
        : "r"((a)[0]), "r"((a)[1]), "r"((a)[2]), "r"((a)[3]), "r"((bf).x), "r"((bf).y))

__device__ __forceinline__ uint32_t enc_h(float v) {
    return (uint32_t)__half_as_ushort(__float2half_rn(v));
}

// ---------------- prep kernels ----------------
__global__ void zero_kernel() {
    int i = blockIdx.x * blockDim.x + threadIdx.x;
    if (i < NTOT) { g_h[0][i] = __float2half(0.f); g_h[1][i] = __float2half(0.f); }
    if (i < NC) g_c[i] = 0.f;
}

__global__ void pad_x_kernel(const float* __restrict__ x) {
    long i = (long)blockIdx.x * blockDim.x + threadIdx.x;
    if (i >= XTOT) return;
    int ci = (int)(i & 31);
    long p = i >> 5;
    float v = 0.f;
    if (p >= GRD && p < GRD + (long)BBATCH * TT * PPX) {
        long pp = p - GRD;
        int bt = (int)(pp / PPX), q = (int)(pp % PPX);
        int py = q / 66, px = q % 66;
        if (py >= 1 && py <= 64 && px >= 1 && px <= 64)
            v = x[(((long)bt * 4096) + (py - 1) * 64 + (px - 1)) * 32 + ci];
    }
    g_x[i] = __float2half_rn(v);
}

__global__ void prep_w_kernel(const float* __restrict__ Wx, const float* __restrict__ Wh) {
    int idx = blockIdx.x * blockDim.x + threadIdx.x;
    if (idx < 36864) {                    // Wh fragments: tap(9) x chunk(4)
        int tap   = idx >> 12;
        int r     = idx & 4095;
        int chunk = r >> 10;
        int r3    = r & 1023;
        int nt    = r3 >> 5, lane = r3 & 31;
        int k0 = chunk * 16 + (lane & 3) * 2;
        int n  = nt * 8 + (lane >> 2);
        float v00 = Wh[((size_t)tap * 64 + k0    ) * 256 + n];
        float v01 = Wh[((size_t)tap * 64 + k0 + 1) * 256 + n];
        float v10 = Wh[((size_t)tap * 64 + k0 + 8) * 256 + n];
        float v11 = Wh[((size_t)tap * 64 + k0 + 9) * 256 + n];
        uint2 o;
        o.x = enc_h(v00) | (enc_h(v01) << 16);
        o.y = enc_h(v10) | (enc_h(v11) << 16);
        g_WhF[idx] = o;
    } else if (idx < 36864 + 18432) {     // Wx fragments: tap(9) x chunk(2)
        int j     = idx - 36864;
        int tap   = j >> 11;
        int r     = j & 2047;
        int chunk = r >> 10;
        int r3    = r & 1023;
        int nt    = r3 >> 5, lane = r3 & 31;
        int k0 = chunk * 16 + (lane & 3) * 2;
        int n  = nt * 8 + (lane >> 2);
        float v00 = Wx[((size_t)tap * 32 + k0    ) * 256 + n];
        float v01 = Wx[((size_t)tap * 32 + k0 + 1) * 256 + n];
        float v10 = Wx[((size_t)tap * 32 + k0 + 8) * 256 + n];
        float v11 = Wx[((size_t)tap * 32 + k0 + 9) * 256 + n];
        uint2 o;
        o.x = enc_h(v00) | (enc_h(v01) << 16);
        o.y = enc_h(v10) | (enc_h(v11) << 16);
        g_WxF[j] = o;
    }
}

// ---------------- xconv: zx = conv3x3(x, Wx) + bias, fp16 out, all frames ---
// 64-pixel tiles, 256 threads, 8 warps (1Mx8N).
// smem: phase 1: x slab 198 rows x 80B = 15840 (aliases z region)
//       phase 2: z16 64 rows x 528B = 33792
//       bias[256] fp32 at 33792
#define XC_BIAS  33792
#define XC_SMEM  34816

__global__ void __launch_bounds__(256, 2)
xconv_kernel(const float* __restrict__ bias)
{
    extern __shared__ __align__(16) char smem[];
    float* bsx = (float*)(smem + XC_BIAS);

    const int tid  = threadIdx.x;
    const int lane = tid & 31;
    const int wn   = tid >> 5;      // 0..7
    const int bt   = blockIdx.y;
    const int q0   = blockIdx.x * 64;

    bsx[tid] = bias[tid];

    // ---- load x slab (padded rows q0-67 .. q0+130) ----
    {
        long offx = (long)GRD * 32 + ((long)bt * PPX + q0 - 67) * 32;
        const uint4* xh = (const uint4*)(g_x + offx);
        for (int i = tid; i < 792; i += 256) {
            int r = i >> 2, c = i & 3;
            *(uint4*)(smem + r * 80 + c * 16) = xh[i];
        }
    }
    __syncthreads();

    float acc[4][4][4];
#pragma unroll
    for (int mt = 0; mt < 4; ++mt)
#pragma unroll
        for (int nt = 0; nt < 4; ++nt)
#pragma unroll
            for (int e = 0; e < 4; ++e) acc[mt][nt][e] = 0.f;

    const uint32_t sx_u = smem_u32(smem);
    const int rowA = lane & 15;
    const int colh = (lane >> 4) * 16;
    const uint2* pbase = g_WxF + wn * 128 + lane;

    uint2 bcur[4], bnxt[4];
#pragma unroll
    for (int nt = 0; nt < 4; ++nt) bcur[nt] = pbase[nt * 32];

#pragma unroll 2
    for (int tc = 0; tc < 18; ++tc) {
        const uint2* pn = pbase + (size_t)(tc + 1 < 18 ? tc + 1 : 17) * 1024;
#pragma unroll
        for (int nt = 0; nt < 4; ++nt) bnxt[nt] = pn[nt * 32];

        const int tap = tc >> 1, chunk = tc & 1;
        const int shift = (tap / 3) * 66 + (tap % 3);
        const uint32_t a_base = sx_u + (uint32_t)(shift + rowA) * 80 + colh + chunk * 32;
#pragma unroll
        for (int mt = 0; mt < 4; ++mt) {
            uint32_t ah[4];
            LDMX4(ah, a_base + mt * (16 * 80));
#pragma unroll
            for (int nt = 0; nt < 4; ++nt) MMA_FP16(acc[mt][nt], ah, bcur[nt]);
        }
#pragma unroll
        for (int nt = 0; nt < 4; ++nt) bcur[nt] = bnxt[nt];
    }

    __syncthreads();   // done reading slab; z16 aliases it

    // ---- scatter z (+bias) to smem as fp16, stride 264 halves ----
#pragma unroll
    for (int mt = 0; mt < 4; ++mt)
#pragma unroll
        for (int nt = 0; nt < 4; ++nt) {
            int px = mt * 16 + (lane >> 2);
            int n  = wn * 32 + nt * 8 + (lane & 3) * 2;
            float b0 = bsx[n], b1 = bsx[n + 1];
            *(__half2*)(smem + px * 528 + n * 2) =
                __floats2half2_rn(acc[mt][nt][0] + b0, acc[mt][nt][1] + b1);
            *(__half2*)(smem + (px + 8) * 528 + n * 2) =
                __floats2half2_rn(acc[mt][nt][2] + b0, acc[mt][nt][3] + b1);
        }
    __syncthreads();

    // ---- coalesced fp16 store to gmem (32KB per CTA) ----
    uint32_t* dst = (uint32_t*)(g_zx + ((size_t)bt * NSTRIP + blockIdx.x) * 16384);
    for (int i = tid; i < 8192; i += 256) {
        int row = i >> 7, c = i & 127;
        dst[i] = *(const uint32_t*)(smem + row * 528 + c * 4);
    }
}

// ---------------- fused ConvLSTM step (h-conv only, mma.sync fp16) ----------
// 64-pixel tiles, 256 threads, 8 warps (1Mx8N), 2 CTAs/SM.
// smem layout (bytes):
//   phase 1 (conv):   [0     : 28512) h slab  198 rows x 144B
//   phase 2 (epilog): [0     : 66560) z 64 rows x 260 fp32  (aliases slab)
//   always:           [66560 : 74752) Wp[32][64] fp32
//                     [74752 : 75008) bp[64] fp32
#define SM_WP    66560
#define SM_BP    74752
#define SM_TOTAL 75008

__global__ void __launch_bounds__(256, 2)
step_kernel(const float* __restrict__ Wp, const float* __restrict__ bp,
            const float* __restrict__ xin, float* __restrict__ out, int t)
{
    extern __shared__ __align__(16) char smem[];
    float* zs   = (float*)smem;
    float* wp_s = (float*)(smem + SM_WP);
    float* bp_s = (float*)(smem + SM_BP);

    const int tid  = threadIdx.x;
    const int lane = tid & 31;
    const int wn   = tid >> 5;      // 0..7
    const int b    = blockIdx.y;
    const int q0   = blockIdx.x * 64;
    const int bt   = b * TT + t;

    for (int i = tid; i < 2048; i += 256) wp_s[i] = Wp[i];
    if (tid < 64) bp_s[tid] = bp[tid];

    // ---- load h slab (padded rows q0-67 .. q0+130) ----
    {
        long off = (long)GRD * 64 + ((long)b * PPX + q0 - 67) * 64;
        const uint4* sh = (const uint4*)(g_h[t & 1] + off);
        for (int i = tid; i < 1584; i += 256) {
            int r = i >> 3, c = i & 7;
            *(uint4*)(smem + r * 144 + c * 16) = sh[i];
        }
    }
    __syncthreads();

    float acc[4][4][4];
#pragma unroll
    for (int mt = 0; mt < 4; ++mt)
#pragma unroll
        for (int nt = 0; nt < 4; ++nt)
#pragma unroll
            for (int e = 0; e < 4; ++e) acc[mt][nt][e] = 0.f;

    const uint32_t sh_u = smem_u32(smem);
    const int rowA = lane & 15;
    const int colh = (lane >> 4) * 16;
    const uint2* pbase = g_WhF + wn * 128 + lane;

    uint2 bcur[4], bnxt[4];
#pragma unroll
    for (int nt = 0; nt < 4; ++nt) bcur[nt] = pbase[nt * 32];

    // ---- h taps: 36 (tap,chunk) pairs, B prefetch double-buffered ----
#pragma unroll 2
    for (int tc = 0; tc < 36; ++tc) {
        const uint2* pn = pbase + (size_t)(tc + 1 < 36 ? tc + 1 : 35) * 1024;
#pragma unroll
        for (int nt = 0; nt < 4; ++nt) bnxt[nt] = pn[nt * 32];

        const int tap = tc >> 2, chunk = tc & 3;
        const int shift = (tap / 3) * 66 + (tap % 3);
        const uint32_t a_base = sh_u + (uint32_t)(shift + rowA) * 144 + colh + chunk * 32;
#pragma unroll
        for (int mt = 0; mt < 4; ++mt) {
            uint32_t ah[4];
            LDMX4(ah, a_base + mt * (16 * 144));
#pragma unroll
            for (int nt = 0; nt < 4; ++nt) MMA_FP16(acc[mt][nt], ah, bcur[nt]);
        }
#pragma unroll
        for (int nt = 0; nt < 4; ++nt) bcur[nt] = bnxt[nt];
    }

    __syncthreads();   // done reading slab; z aliases it

    // ---- scatter z to smem ----
#pragma unroll
    for (int mt = 0; mt < 4; ++mt)
#pragma unroll
        for (int nt = 0; nt < 4; ++nt) {
            int px = mt * 16 + (lane >> 2);
            int n  = wn * 32 + nt * 8 + (lane & 3) * 2;
            *(float2*)(zs + px * 260 + n)       = make_float2(acc[mt][nt][0], acc[mt][nt][1]);
            *(float2*)(zs + (px + 8) * 260 + n) = make_float2(acc[mt][nt][2], acc[mt][nt][3]);
        }
    __syncthreads();

    // ---- epilogue: zx(fp16,+bias) + gates, c/h update, fused 1x1 residual ----
    const int pxl = tid >> 2;          // 0..63
    const int q   = q0 + pxl;
    const int py  = q / 66, pxc = q % 66;
    const bool inter = (q < PPX) && py >= 1 && py <= 64 && pxc >= 1 && pxc <= 64;
    if (inter) {
        float* cpt = g_c + ((size_t)b * PPX + q) * 64;
        unsigned short* ho = (unsigned short*)(g_h[(t + 1) & 1] + GRD * 64 + ((size_t)b * PPX + q) * 64);
        float* op = out + ((size_t)bt * 4096 + (py - 1) * 64 + (pxc - 1)) * 64;
        const float* zrow  = zs + pxl * 260;
        const __half* zxrow = g_zx + (((size_t)bt * NSTRIP + blockIdx.x) * 64 + pxl) * 256;
        const float* xrow  = xin + ((size_t)bt * 4096 + (py - 1) * 64 + (pxc - 1)) * 32;
        const int f0base = (tid & 3) * 16;

        float4 xr[8];
#pragma unroll
        for (int i = 0; i < 8; ++i) xr[i] = __ldg((const float4*)xrow + i);

#pragma unroll
        for (int j4 = 0; j4 < 4; ++j4) {
            int f0 = f0base + j4 * 4;
            // residual: res = bp + x . Wp[:, f0:f0+4]
            float4 res = *(const float4*)(bp_s + f0);
#pragma unroll
            for (int ci4 = 0; ci4 < 8; ++ci4) {
                const float* xv = &xr[ci4].x;
#pragma unroll
                for (int cc = 0; cc < 4; ++cc) {
                    float4 w = *(const float4*)(wp_s + (ci4 * 4 + cc) * 64 + f0);
                    float xs = xv[cc];
                    res.x = fmaf(xs, w.x, res.x);
                    res.y = fmaf(xs, w.y, res.y);
                    res.z = fmaf(xs, w.z, res.z);
                    res.w = fmaf(xs, w.w, res.w);
                }
            }

            float4 zi = *(const float4*)(zrow + f0);
            float4 zf = *(const float4*)(zrow + 64 + f0);
            float4 zc = *(const float4*)(zrow + 128 + f0);
            float4 zo = *(const float4*)(zrow + 192 + f0);

            // zx fp16 loads (bias already folded in)
            uint2 uxi = __ldg((const uint2*)(zxrow + f0));
            uint2 uxf = __ldg((const uint2*)(zxrow + 64 + f0));
            uint2 uxc = __ldg((const uint2*)(zxrow + 128 + f0));
            uint2 uxo = __ldg((const uint2*)(zxrow + 192 + f0));
            float2 xi0 = __half22float2(*(__half2*)&uxi.x), xi1 = __half22float2(*(__half2*)&uxi.y);
            float2 xf0 = __half22float2(*(__half2*)&uxf.x), xf1 = __half22float2(*(__half2*)&uxf.y);
            float2 xc0 = __half22float2(*(__half2*)&uxc.x), xc1 = __half22float2(*(__half2*)&uxc.y);
            float2 xo0 = __half22float2(*(__half2*)&uxo.x), xo1 = __half22float2(*(__half2*)&uxo.y);
            float xiv[4] = {xi0.x, xi0.y, xi1.x, xi1.y};
            float xfv[4] = {xf0.x, xf0.y, xf1.x, xf1.y};
            float xcv[4] = {xc0.x, xc0.y, xc1.x, xc1.y};
            float xov[4] = {xo0.x, xo0.y, xo1.x, xo1.y};

            float4 c4 = *(float4*)(cpt + f0);
            float4 o4;
            unsigned short hh[4];
#pragma unroll
            for (int e = 0; e < 4; ++e) {
                float vi = (&zi.x)[e] + xiv[e];
                float vf = (&zf.x)[e] + xfv[e];
                float vc = (&zc.x)[e] + xcv[e];
                float vo = (&zo.x)[e] + xov[e];
                float ig = __saturatef(fmaf(0.2f, vi, 0.5f));
                float fg = __saturatef(fmaf(0.2f, vf, 0.5f));
                float og = __saturatef(fmaf(0.2f, vo, 0.5f));
                float cn = fmaf(fg, (&c4.x)[e], ig * tanhf(vc));
                (&c4.x)[e] = cn;
                float hv = og * tanhf(cn);
                (&o4.x)[e] = hv + (&res.x)[e];
                hh[e] = __half_as_ushort(__float2half_rn(hv));
            }
            *(float4*)(cpt + f0) = c4;
            *(float4*)(op + f0)  = o4;
            uint2 phv = make_uint2((uint32_t)hh[0] | ((uint32_t)hh[1] << 16),
                                   (uint32_t)hh[2] | ((uint32_t)hh[3] << 16));
            *(uint2*)(ho + f0) = phv;
        }
    }
}

// ---------------------------------------------------------------------------
extern "C" void kernel_launch(void* const* d_in, const int* in_sizes, int n_in,
                              void* d_out, int out_size)
{
    const float* x  = (const float*)d_in[0];
    const float* Wx = (const float*)d_in[1];
    const float* Wh = (const float*)d_in[2];
    const float* b  = (const float*)d_in[3];
    const float* Wp = (const float*)d_in[4];
    const float* bp = (const float*)d_in[5];
    float* out = (float*)d_out;

    cudaFuncSetAttribute(step_kernel,
                         cudaFuncAttributeMaxDynamicSharedMemorySize, SM_TOTAL);
    cudaFuncSetAttribute(xconv_kernel,
                         cudaFuncAttributeMaxDynamicSharedMemorySize, XC_SMEM);

    zero_kernel<<<(NTOT + 255) / 256, 256>>>();
    pad_x_kernel<<<(int)((XTOT + 255) / 256), 256>>>(x);
    prep_w_kernel<<<(36864 + 18432 + 255) / 256, 256>>>(Wx, Wh);

    dim3 xgrid(NSTRIP, BBATCH * TT);
    xconv_kernel<<<xgrid, 256, XC_SMEM>>>(b);

    dim3 grid(NSTRIP, BBATCH);
    for (int t = 0; t < TT; ++t)
        step_kernel<<<grid, 256, SM_TOTAL>>>(Wp, bp, x, out, t);
}

// round 14
// speedup vs baseline: 1.6300x; 1.0570x over previous
#include <cuda_runtime.h>
#include <cuda_fp16.h>
#include <cstdint>
#include <math.h>

#define BBATCH 4
#define TT   16
#define PPX  4356          // 66*66 padded pixels
#define GRD  192           // guard pixels at both ends of padded arrays
#define NTOT ((2*GRD + BBATCH*PPX) * 64)
#define XTOT ((2*GRD + BBATCH*TT*PPX) * 32)
#define NSTRIP 70          // 64-pixel strips
#define NBLK (NSTRIP * BBATCH)                    // 280 persistent CTAs
#define ZXN  (BBATCH * TT * NSTRIP * 64 * 256)    // halves

// ---------------- static device state ----------------
__device__ __half g_h[2][NTOT];          // hidden state, single fp16 plane
__device__ __half g_x[XTOT];             // padded input, single fp16 plane
__device__ __half g_zx[ZXN];             // precomputed x-conv + bias, fp16
__device__ unsigned g_bar;               // persistent-kernel barrier counter
// mma.sync B fragments (single fp16 plane), lane-ordered:
__device__ uint2 g_WhF[9 * 4 * 32 * 32];
__device__ uint2 g_WxF[9 * 2 * 32 * 32];

// ---------------- helpers ----------------
__device__ __forceinline__ uint32_t smem_u32(const void* p) {
    uint32_t a;
    asm("{ .reg .u64 t; cvta.to.shared.u64 t, %1; cvt.u32.u64 %0, t; }" : "=r"(a) : "l"(p));
    return a;
}
__device__ __forceinline__ uint4 ldcg4(const uint4* p) {
    uint4 v;
    asm volatile("ld.global.cg.v4.u32 {%0,%1,%2,%3}, [%4];"
        : "=r"(v.x), "=r"(v.y), "=r"(v.z), "=r"(v.w) : "l"(p));
    return v;
}
__device__ __forceinline__ unsigned ld_vol(const unsigned* p) {
    unsigned v; asm volatile("ld.volatile.global.u32 %0, [%1];" : "=r"(v) : "l"(p)); return v;
}

#define LDMX4(r, addr) \
    asm volatile("ldmatrix.sync.aligned.m8n8.x4.shared.b16 {%0,%1,%2,%3}, [%4];" \
        : "=r"((r)[0]), "=r"((r)[1]), "=r"((r)[2]), "=r"((r)[3]) : "r"(addr))

#define MMA_FP16(d, a, bf) \
    asm volatile("mma.sync.aligned.m16n8k16.row.col.f32.f16.f16.f32 " \
        "{%0,%1,%2,%3}, {%4,%5,%6,%7}, {%8,%9}, {%0,%1,%2,%3};" \
        : "+f"((d)[0]), "+f"((d)[1]), "+f"((d)[2]), "+f"((d)[3]) \
        : "r"((a)[0]), "r"((a)[1]), "r"((a)[2]), "r"((a)[3]), "r"((bf).x), "r"((bf).y))

__device__ __forceinline__ uint32_t enc_h(float v) {
    return (uint32_t)__half_as_ushort(__float2half_rn(v));
}

// ---------------- prep kernels ----------------
__global__ void zero_kernel() {
    int i = blockIdx.x * blockDim.x + threadIdx.x;
    if (i < NTOT) { g_h[0][i] = __float2half(0.f); g_h[1][i] = __float2half(0.f); }
    if (i == 0) g_bar = 0u;
}

__global__ void pad_x_kernel(const float* __restrict__ x) {
    long i = (long)blockIdx.x * blockDim.x + threadIdx.x;
    if (i >= XTOT) return;
    int ci = (int)(i & 31);
    long p = i >> 5;
    float v = 0.f;
    if (p >= GRD && p < GRD + (long)BBATCH * TT * PPX) {
        long pp = p - GRD;
        int bt = (int)(pp / PPX), q = (int)(pp % PPX);
        int py = q / 66, px = q % 66;
        if (py >= 1 && py <= 64 && px >= 1 && px <= 64)
            v = x[(((long)bt * 4096) + (py - 1) * 64 + (px - 1)) * 32 + ci];
    }
    g_x[i] = __float2half_rn(v);
}

__global__ void prep_w_kernel(const float* __restrict__ Wx, const float* __restrict__ Wh) {
    int idx = blockIdx.x * blockDim.x + threadIdx.x;
    if (idx < 36864) {                    // Wh fragments: tap(9) x chunk(4)
        int tap   = idx >> 12;
        int r     = idx & 4095;
        int chunk = r >> 10;
        int r3    = r & 1023;
        int nt    = r3 >> 5, lane = r3 & 31;
        int k0 = chunk * 16 + (lane & 3) * 2;
        int n  = nt * 8 + (lane >> 2);
        float v00 = Wh[((size_t)tap * 64 + k0    ) * 256 + n];
        float v01 = Wh[((size_t)tap * 64 + k0 + 1) * 256 + n];
        float v10 = Wh[((size_t)tap * 64 + k0 + 8) * 256 + n];
        float v11 = Wh[((size_t)tap * 64 + k0 + 9) * 256 + n];
        uint2 o;
        o.x = enc_h(v00) | (enc_h(v01) << 16);
        o.y = enc_h(v10) | (enc_h(v11) << 16);
        g_WhF[idx] = o;
    } else if (idx < 36864 + 18432) {     // Wx fragments: tap(9) x chunk(2)
        int j     = idx - 36864;
        int tap   = j >> 11;
        int r     = j & 2047;
        int chunk = r >> 10;
        int r3    = r & 1023;
        int nt    = r3 >> 5, lane = r3 & 31;
        int k0 = chunk * 16 + (lane & 3) * 2;
        int n  = nt * 8 + (lane >> 2);
        float v00 = Wx[((size_t)tap * 32 + k0    ) * 256 + n];
        float v01 = Wx[((size_t)tap * 32 + k0 + 1) * 256 + n];
        float v10 = Wx[((size_t)tap * 32 + k0 + 8) * 256 + n];
        float v11 = Wx[((size_t)tap * 32 + k0 + 9) * 256 + n];
        uint2 o;
        o.x = enc_h(v00) | (enc_h(v01) << 16);
        o.y = enc_h(v10) | (enc_h(v11) << 16);
        g_WxF[j] = o;
    }
}

// ---------------- xconv: zx = conv3x3(x, Wx) + bias, fp16 out, all frames ---
// 64-pixel tiles, 256 threads, 8 warps (1Mx8N), 2 CTAs/SM.
#define XC_BIAS  33792
#define XC_SMEM  34816

__global__ void __launch_bounds__(256, 2)
xconv_kernel(const float* __restrict__ bias)
{
    extern __shared__ __align__(16) char smem[];
    float* bsx = (float*)(smem + XC_BIAS);

    const int tid  = threadIdx.x;
    const int lane = tid & 31;
    const int wn   = tid >> 5;      // 0..7
    const int bt   = blockIdx.y;
    const int q0   = blockIdx.x * 64;

    bsx[tid] = bias[tid];

    // ---- load x slab (padded rows q0-67 .. q0+130) ----
    {
        long offx = (long)GRD * 32 + ((long)bt * PPX + q0 - 67) * 32;
        const uint4* xh = (const uint4*)(g_x + offx);
        for (int i = tid; i < 792; i += 256) {
            int r = i >> 2, c = i & 3;
            *(uint4*)(smem + r * 80 + c * 16) = xh[i];
        }
    }
    __syncthreads();

    float acc[4][4][4];
#pragma unroll
    for (int mt = 0; mt < 4; ++mt)
#pragma unroll
        for (int nt = 0; nt < 4; ++nt)
#pragma unroll
            for (int e = 0; e < 4; ++e) acc[mt][nt][e] = 0.f;

    const uint32_t sx_u = smem_u32(smem);
    const int rowA = lane & 15;
    const int colh = (lane >> 4) * 16;
    const uint2* pbase = g_WxF + wn * 128 + lane;

    uint2 bcur[4], bnxt[4];
#pragma unroll
    for (int nt = 0; nt < 4; ++nt) bcur[nt] = pbase[nt * 32];

#pragma unroll 2
    for (int tc = 0; tc < 18; ++tc) {
        const uint2* pn = pbase + (size_t)(tc + 1 < 18 ? tc + 1 : 17) * 1024;
#pragma unroll
        for (int nt = 0; nt < 4; ++nt) bnxt[nt] = pn[nt * 32];

        const int tap = tc >> 1, chunk = tc & 1;
        const int shift = (tap / 3) * 66 + (tap % 3);
        const uint32_t a_base = sx_u + (uint32_t)(shift + rowA) * 80 + colh + chunk * 32;
#pragma unroll
        for (int mt = 0; mt < 4; ++mt) {
            uint32_t ah[4];
            LDMX4(ah, a_base + mt * (16 * 80));
#pragma unroll
            for (int nt = 0; nt < 4; ++nt) MMA_FP16(acc[mt][nt], ah, bcur[nt]);
        }
#pragma unroll
        for (int nt = 0; nt < 4; ++nt) bcur[nt] = bnxt[nt];
    }

    __syncthreads();   // done reading slab; z16 aliases it

#pragma unroll
    for (int mt = 0; mt < 4; ++mt)
#pragma unroll
        for (int nt = 0; nt < 4; ++nt) {
            int px = mt * 16 + (lane >> 2);
            int n  = wn * 32 + nt * 8 + (lane & 3) * 2;
            float b0 = bsx[n], b1 = bsx[n + 1];
            *(__half2*)(smem + px * 528 + n * 2) =
                __floats2half2_rn(acc[mt][nt][0] + b0, acc[mt][nt][1] + b1);
            *(__half2*)(smem + (px + 8) * 528 + n * 2) =
                __floats2half2_rn(acc[mt][nt][2] + b0, acc[mt][nt][3] + b1);
        }
    __syncthreads();

    uint32_t* dst = (uint32_t*)(g_zx + ((size_t)bt * NSTRIP + blockIdx.x) * 16384);
    for (int i = tid; i < 8192; i += 256) {
        int row = i >> 7, c = i & 127;
        dst[i] = *(const uint32_t*)(smem + row * 528 + c * 4);
    }
}

// ---------------- persistent ConvLSTM: all 16 steps, device barrier ----------
// 64-pixel tiles, 256 threads, 8 warps, 2 CTAs/SM -> 280 CTAs all resident.
// smem layout (bytes):
//   phase 1 (conv):   [0     : 28512) h slab  198 rows x 144B
//   phase 2 (epilog): [0     : 66560) z 64 rows x 260 fp32  (aliases slab)
//   always:           [66560 : 74752) Wp[32][64] fp32
//                     [74752 : 75008) bp[64] fp32
//                     [75008 : 91392) c[64][64] fp32 (persists across steps)
#define SM_WP    66560
#define SM_BP    74752
#define SM_C     75008
#define SM_TOTAL 91392

__global__ void __launch_bounds__(256, 2)
step_all_kernel(const float* __restrict__ Wp, const float* __restrict__ bp,
                const float* __restrict__ xin, float* __restrict__ out)
{
    extern __shared__ __align__(16) char smem[];
    float* zs   = (float*)smem;
    float* wp_s = (float*)(smem + SM_WP);
    float* bp_s = (float*)(smem + SM_BP);
    float* c_s  = (float*)(smem + SM_C);

    const int tid  = threadIdx.x;
    const int lane = tid & 31;
    const int wn   = tid >> 5;      // 0..7
    const int b    = blockIdx.y;
    const int q0   = blockIdx.x * 64;

    for (int i = tid; i < 2048; i += 256) wp_s[i] = Wp[i];
    if (tid < 64) bp_s[tid] = bp[tid];
    for (int i = tid; i < 4096; i += 256) c_s[i] = 0.f;

    const uint32_t sh_u = smem_u32(smem);
    const int rowA = lane & 15;
    const int colh = (lane >> 4) * 16;
    const uint2* pbase = g_WhF + wn * 128 + lane;

    // epilogue constants
    const int pxl = tid >> 2;          // 0..63
    const int q   = q0 + pxl;
    const int py  = q / 66, pxc = q % 66;
    const bool inter = (q < PPX) && py >= 1 && py <= 64 && pxc >= 1 && pxc <= 64;
    const int f0base = (tid & 3) * 16;

    for (int t = 0; t < TT; ++t) {
        const int bt = b * TT + t;

        // ---- load h slab (L2-only: L1 not coherent across persistent steps) ----
        {
            long off = (long)GRD * 64 + ((long)b * PPX + q0 - 67) * 64;
            const uint4* sh = (const uint4*)(g_h[t & 1] + off);
            for (int i = tid; i < 1584; i += 256) {
                int r = i >> 3, c = i & 7;
                *(uint4*)(smem + r * 144 + c * 16) = ldcg4(sh + i);
            }
        }
        __syncthreads();

        float acc[4][4][4];
#pragma unroll
        for (int mt = 0; mt < 4; ++mt)
#pragma unroll
            for (int nt = 0; nt < 4; ++nt)
#pragma unroll
                for (int e = 0; e < 4; ++e) acc[mt][nt][e] = 0.f;

        uint2 bcur[4], bnxt[4];
#pragma unroll
        for (int nt = 0; nt < 4; ++nt) bcur[nt] = pbase[nt * 32];

        // ---- h taps: 36 (tap,chunk) pairs, B prefetch double-buffered ----
#pragma unroll 2
        for (int tc = 0; tc < 36; ++tc) {
            const uint2* pn = pbase + (size_t)(tc + 1 < 36 ? tc + 1 : 35) * 1024;
#pragma unroll
            for (int nt = 0; nt < 4; ++nt) bnxt[nt] = pn[nt * 32];

            const int tap = tc >> 2, chunk = tc & 3;
            const int shift = (tap / 3) * 66 + (tap % 3);
            const uint32_t a_base = sh_u + (uint32_t)(shift + rowA) * 144 + colh + chunk * 32;
#pragma unroll
            for (int mt = 0; mt < 4; ++mt) {
                uint32_t ah[4];
                LDMX4(ah, a_base + mt * (16 * 144));
#pragma unroll
                for (int nt = 0; nt < 4; ++nt) MMA_FP16(acc[mt][nt], ah, bcur[nt]);
            }
#pragma unroll
            for (int nt = 0; nt < 4; ++nt) bcur[nt] = bnxt[nt];
        }

        __syncthreads();   // done reading slab; z aliases it

        // ---- scatter z to smem ----
#pragma unroll
        for (int mt = 0; mt < 4; ++mt)
#pragma unroll
            for (int nt = 0; nt < 4; ++nt) {
                int px = mt * 16 + (lane >> 2);
                int n  = wn * 32 + nt * 8 + (lane & 3) * 2;
                *(float2*)(zs + px * 260 + n)       = make_float2(acc[mt][nt][0], acc[mt][nt][1]);
                *(float2*)(zs + (px + 8) * 260 + n) = make_float2(acc[mt][nt][2], acc[mt][nt][3]);
            }
        __syncthreads();

        // ---- epilogue ----
        if (inter) {
            unsigned short* ho = (unsigned short*)(g_h[(t + 1) & 1] + GRD * 64 + ((size_t)b * PPX + q) * 64);
            float* op = out + ((size_t)bt * 4096 + (py - 1) * 64 + (pxc - 1)) * 64;
            const float* zrow  = zs + pxl * 260;
            const __half* zxrow = g_zx + (((size_t)bt * NSTRIP + blockIdx.x) * 64 + pxl) * 256;
            const float* xrow  = xin + ((size_t)bt * 4096 + (py - 1) * 64 + (pxc - 1)) * 32;
            float* crow = c_s + pxl * 64;

            float4 xr[8];
#pragma unroll
            for (int i = 0; i < 8; ++i) xr[i] = __ldg((const float4*)xrow + i);

#pragma unroll
            for (int j4 = 0; j4 < 4; ++j4) {
                int f0 = f0base + j4 * 4;
                float4 res = *(const float4*)(bp_s + f0);
#pragma unroll
                for (int ci4 = 0; ci4 < 8; ++ci4) {
                    const float* xv = &xr[ci4].x;
#pragma unroll
                    for (int cc = 0; cc < 4; ++cc) {
                        float4 w = *(const float4*)(wp_s + (ci4 * 4 + cc) * 64 + f0);
                        float xs = xv[cc];
                        res.x = fmaf(xs, w.x, res.x);
                        res.y = fmaf(xs, w.y, res.y);
                        res.z = fmaf(xs, w.z, res.z);
                        res.w = fmaf(xs, w.w, res.w);
                    }
                }

                float4 zi = *(const float4*)(zrow + f0);
                float4 zf = *(const float4*)(zrow + 64 + f0);
                float4 zc = *(const float4*)(zrow + 128 + f0);
                float4 zo = *(const float4*)(zrow + 192 + f0);

                uint2 uxi = __ldg((const uint2*)(zxrow + f0));
                uint2 uxf = __ldg((const uint2*)(zxrow + 64 + f0));
                uint2 uxc = __ldg((const uint2*)(zxrow + 128 + f0));
                uint2 uxo = __ldg((const uint2*)(zxrow + 192 + f0));
                float2 xi0 = __half22float2(*(__half2*)&uxi.x), xi1 = __half22float2(*(__half2*)&uxi.y);
                float2 xf0 = __half22float2(*(__half2*)&uxf.x), xf1 = __half22float2(*(__half2*)&uxf.y);
                float2 xc0 = __half22float2(*(__half2*)&uxc.x), xc1 = __half22float2(*(__half2*)&uxc.y);
                float2 xo0 = __half22float2(*(__half2*)&uxo.x), xo1 = __half22float2(*(__half2*)&uxo.y);
                float xiv[4] = {xi0.x, xi0.y, xi1.x, xi1.y};
                float xfv[4] = {xf0.x, xf0.y, xf1.x, xf1.y};
                float xcv[4] = {xc0.x, xc0.y, xc1.x, xc1.y};
                float xov[4] = {xo0.x, xo0.y, xo1.x, xo1.y};

                float4 c4 = *(float4*)(crow + f0);
                float4 o4;
                unsigned short hh[4];
#pragma unroll
                for (int e = 0; e < 4; ++e) {
                    float vi = (&zi.x)[e] + xiv[e];
                    float vf = (&zf.x)[e] + xfv[e];
                    float vc = (&zc.x)[e] + xcv[e];
                    float vo = (&zo.x)[e] + xov[e];
                    float ig = __saturatef(fmaf(0.2f, vi, 0.5f));
                    float fg = __saturatef(fmaf(0.2f, vf, 0.5f));
                    float og = __saturatef(fmaf(0.2f, vo, 0.5f));
                    float cn = fmaf(fg, (&c4.x)[e], ig * tanhf(vc));
                    (&c4.x)[e] = cn;
                    float hv = og * tanhf(cn);
                    (&o4.x)[e] = hv + (&res.x)[e];
                    hh[e] = __half_as_ushort(__float2half_rn(hv));
                }
                *(float4*)(crow + f0) = c4;
                *(float4*)(op + f0)   = o4;
                uint2 phv = make_uint2((uint32_t)hh[0] | ((uint32_t)hh[1] << 16),
                                       (uint32_t)hh[2] | ((uint32_t)hh[3] << 16));
                *(uint2*)(ho + f0) = phv;
            }
        }

        // ---- device-wide barrier (release h[t+1] to all CTAs) ----
        __threadfence();
        __syncthreads();
        if (tid == 0) {
            atomicAdd(&g_bar, 1u);
            const unsigned target = (unsigned)NBLK * (unsigned)(t + 1);
            while (ld_vol(&g_bar) < target) { __nanosleep(64); }
        }
        __syncthreads();
        __threadfence();
    }
}

// ---------------------------------------------------------------------------
extern "C" void kernel_launch(void* const* d_in, const int* in_sizes, int n_in,
                              void* d_out, int out_size)
{
    const float* x  = (const float*)d_in[0];
    const float* Wx = (const float*)d_in[1];
    const float* Wh = (const float*)d_in[2];
    const float* b  = (const float*)d_in[3];
    const float* Wp = (const float*)d_in[4];
    const float* bp = (const float*)d_in[5];
    float* out = (float*)d_out;

    cudaFuncSetAttribute(step_all_kernel,
                         cudaFuncAttributeMaxDynamicSharedMemorySize, SM_TOTAL);
    cudaFuncSetAttribute(xconv_kernel,
                         cudaFuncAttributeMaxDynamicSharedMemorySize, XC_SMEM);

    zero_kernel<<<(NTOT + 255) / 256, 256>>>();
    pad_x_kernel<<<(int)((XTOT + 255) / 256), 256>>>(x);
    prep_w_kernel<<<(36864 + 18432 + 255) / 256, 256>>>(Wx, Wh);

    dim3 xgrid(NSTRIP, BBATCH * TT);
    xconv_kernel<<<xgrid, 256, XC_SMEM>>>(b);

    dim3 grid(NSTRIP, BBATCH);
    step_all_kernel<<<grid, 256, SM_TOTAL>>>(Wp, bp, x, out);
}

// round 17
// speedup vs baseline: 1.6874x; 1.0352x over previous
#include <cuda_runtime.h>
#include <cuda_fp16.h>
#include <cstdint>
#include <math.h>

#define BBATCH 4
#define TT   16
#define PPX  4356          // 66*66 padded pixels
#define GRD  192           // guard pixels at both ends of padded arrays
#define NTOT ((2*GRD + BBATCH*PPX) * 64)
#define XTOT ((2*GRD + BBATCH*TT*PPX) * 32)
#define NSTRIP 70          // 64-pixel strips
#define NBLK (NSTRIP * BBATCH)                    // 280 persistent CTAs
#define ZXN  (BBATCH * TT * NSTRIP * 64 * 256)    // halves

// ---------------- static device state ----------------
__device__ __half g_h[2][NTOT];          // hidden state, single fp16 plane
__device__ __half g_x[XTOT];             // padded input, single fp16 plane
__device__ __half g_zx[ZXN];             // precomputed x-conv + bias, fp16
__device__ unsigned g_flag[NBLK];        // per-(b,strip) completed-step counters
// mma.sync B fragments (single fp16 plane), lane-ordered:
__device__ uint2 g_WhF[9 * 4 * 32 * 32];
__device__ uint2 g_WxF[9 * 2 * 32 * 32];

// ---------------- helpers ----------------
__device__ __forceinline__ uint32_t smem_u32(const void* p) {
    uint32_t a;
    asm("{ .reg .u64 t; cvta.to.shared.u64 t, %1; cvt.u32.u64 %0, t; }" : "=r"(a) : "l"(p));
    return a;
}
__device__ __forceinline__ uint4 ldcg4(const uint4* p) {
    uint4 v;
    asm volatile("ld.global.cg.v4.u32 {%0,%1,%2,%3}, [%4];"
        : "=r"(v.x), "=r"(v.y), "=r"(v.z), "=r"(v.w) : "l"(p));
    return v;
}
__device__ __forceinline__ unsigned ld_vol(const unsigned* p) {
    unsigned v; asm volatile("ld.volatile.global.u32 %0, [%1];" : "=r"(v) : "l"(p)); return v;
}

#define LDMX4(r, addr) \
    asm volatile("ldmatrix.sync.aligned.m8n8.x4.shared.b16 {%0,%1,%2,%3}, [%4];" \
        : "=r"((r)[0]), "=r"((r)[1]), "=r"((r)[2]), "=r"((r)[3]) : "r"(addr))

#define MMA_FP16(d, a, bf) \
    asm volatile("mma.sync.aligned.m16n8k16.row.col.f32.f16.f16.f32 " \
        "{%0,%1,%2,%3}, {%4,%5,%6,%7}, {%8,%9}, {%0,%1,%2,%3};" \
        : "+f"((d)[0]), "+f"((d)[1]), "+f"((d)[2]), "+f"((d)[3]) \
        : "r"((a)[0]), "r"((a)[1]), "r"((a)[2]), "r"((a)[3]), "r"((bf).x), "r"((bf).y))

__device__ __forceinline__ uint32_t enc_h(float v) {
    return (uint32_t)__half_as_ushort(__float2half_rn(v));
}

// ---------------- prep kernels ----------------
__global__ void zero_kernel() {
    int i = blockIdx.x * blockDim.x + threadIdx.x;
    if (i < NTOT) { g_h[0][i] = __float2half(0.f); g_h[1][i] = __float2half(0.f); }
    if (i < NBLK) g_flag[i] = 0u;
}

__global__ void pad_x_kernel(const float* __restrict__ x) {
    long i = (long)blockIdx.x * blockDim.x + threadIdx.x;
    if (i >= XTOT) return;
    int ci = (int)(i & 31);
    long p = i >> 5;
    float v = 0.f;
    if (p >= GRD && p < GRD + (long)BBATCH * TT * PPX) {
        long pp = p - GRD;
        int bt = (int)(pp / PPX), q = (int)(pp % PPX);
        int py = q / 66, px = q % 66;
        if (py >= 1 && py <= 64 && px >= 1 && px <= 64)
            v = x[(((long)bt * 4096) + (py - 1) * 64 + (px - 1)) * 32 + ci];
    }
    g_x[i] = __float2half_rn(v);
}

__global__ void prep_w_kernel(const float* __restrict__ Wx, const float* __restrict__ Wh) {
    int idx = blockIdx.x * blockDim.x + threadIdx.x;
    if (idx < 36864) {                    // Wh fragments: tap(9) x chunk(4)
        int tap   = idx >> 12;
        int r     = idx & 4095;
        int chunk = r >> 10;
        int r3    = r & 1023;
        int nt    = r3 >> 5, lane = r3 & 31;
        int k0 = chunk * 16 + (lane & 3) * 2;
        int n  = nt * 8 + (lane >> 2);
        float v00 = Wh[((size_t)tap * 64 + k0    ) * 256 + n];
        float v01 = Wh[((size_t)tap * 64 + k0 + 1) * 256 + n];
        float v10 = Wh[((size_t)tap * 64 + k0 + 8) * 256 + n];
        float v11 = Wh[((size_t)tap * 64 + k0 + 9) * 256 + n];
        uint2 o;
        o.x = enc_h(v00) | (enc_h(v01) << 16);
        o.y = enc_h(v10) | (enc_h(v11) << 16);
        g_WhF[idx] = o;
    } else if (idx < 36864 + 18432) {     // Wx fragments: tap(9) x chunk(2)
        int j     = idx - 36864;
        int tap   = j >> 11;
        int r     = j & 2047;
        int chunk = r >> 10;
        int r3    = r & 1023;
        int nt    = r3 >> 5, lane = r3 & 31;
        int k0 = chunk * 16 + (lane & 3) * 2;
        int n  = nt * 8 + (lane >> 2);
        float v00 = Wx[((size_t)tap * 32 + k0    ) * 256 + n];
        float v01 = Wx[((size_t)tap * 32 + k0 + 1) * 256 + n];
        float v10 = Wx[((size_t)tap * 32 + k0 + 8) * 256 + n];
        float v11 = Wx[((size_t)tap * 32 + k0 + 9) * 256 + n];
        uint2 o;
        o.x = enc_h(v00) | (enc_h(v01) << 16);
        o.y = enc_h(v10) | (enc_h(v11) << 16);
        g_WxF[j] = o;
    }
}

// ---------------- xconv: zx = conv3x3(x, Wx) + bias, fp16 out, all frames ---
// 64-pixel tiles, 256 threads, 8 warps (1Mx8N), 2 CTAs/SM.
#define XC_BIAS  33792
#define XC_SMEM  34816

__global__ void __launch_bounds__(256, 2)
xconv_kernel(const float* __restrict__ bias)
{
    extern __shared__ __align__(16) char smem[];
    float* bsx = (float*)(smem + XC_BIAS);

    const int tid  = threadIdx.x;
    const int lane = tid & 31;
    const int wn   = tid >> 5;      // 0..7
    const int bt   = blockIdx.y;
    const int q0   = blockIdx.x * 64;

    bsx[tid] = bias[tid];

    // ---- load x slab (padded rows q0-67 .. q0+130) ----
    {
        long offx = (long)GRD * 32 + ((long)bt * PPX + q0 - 67) * 32;
        const uint4* xh = (const uint4*)(g_x + offx);
        for (int i = tid; i < 792; i += 256) {
            int r = i >> 2, c = i & 3;
            *(uint4*)(smem + r * 80 + c * 16) = xh[i];
        }
    }
    __syncthreads();

    float acc[4][4][4];
#pragma unroll
    for (int mt = 0; mt < 4; ++mt)
#pragma unroll
        for (int nt = 0; nt < 4; ++nt)
#pragma unroll
            for (int e = 0; e < 4; ++e) acc[mt][nt][e] = 0.f;

    const uint32_t sx_u = smem_u32(smem);
    const int rowA = lane & 15;
    const int colh = (lane >> 4) * 16;
    const uint2* pbase = g_WxF + wn * 128 + lane;

    uint2 bcur[4], bnxt[4];
#pragma unroll
    for (int nt = 0; nt < 4; ++nt) bcur[nt] = pbase[nt * 32];

#pragma unroll 2
    for (int tc = 0; tc < 18; ++tc) {
        const uint2* pn = pbase + (size_t)(tc + 1 < 18 ? tc + 1 : 17) * 1024;
#pragma unroll
        for (int nt = 0; nt < 4; ++nt) bnxt[nt] = pn[nt * 32];

        const int tap = tc >> 1, chunk = tc & 1;
        const int shift = (tap / 3) * 66 + (tap % 3);
        const uint32_t a_base = sx_u + (uint32_t)(shift + rowA) * 80 + colh + chunk * 32;
#pragma unroll
        for (int mt = 0; mt < 4; ++mt) {
            uint32_t ah[4];
            LDMX4(ah, a_base + mt * (16 * 80));
#pragma unroll
            for (int nt = 0; nt < 4; ++nt) MMA_FP16(acc[mt][nt], ah, bcur[nt]);
        }
#pragma unroll
        for (int nt = 0; nt < 4; ++nt) bcur[nt] = bnxt[nt];
    }

    __syncthreads();   // done reading slab; z16 aliases it

#pragma unroll
    for (int mt = 0; mt < 4; ++mt)
#pragma unroll
        for (int nt = 0; nt < 4; ++nt) {
            int px = mt * 16 + (lane >> 2);
            int n  = wn * 32 + nt * 8 + (lane & 3) * 2;
            float b0 = bsx[n], b1 = bsx[n + 1];
            *(__half2*)(smem + px * 528 + n * 2) =
                __floats2half2_rn(acc[mt][nt][0] + b0, acc[mt][nt][1] + b1);
            *(__half2*)(smem + (px + 8) * 528 + n * 2) =
                __floats2half2_rn(acc[mt][nt][2] + b0, acc[mt][nt][3] + b1);
        }
    __syncthreads();

    uint32_t* dst = (uint32_t*)(g_zx + ((size_t)bt * NSTRIP + blockIdx.x) * 16384);
    for (int i = tid; i < 8192; i += 256) {
        int row = i >> 7, c = i & 127;
        dst[i] = *(const uint32_t*)(smem + row * 528 + c * 4);
    }
}

// ---------------- persistent ConvLSTM: all 16 steps, neighbor flags ----------
// 64-pixel tiles, 256 threads, 8 warps, 2 CTAs/SM -> 280 CTAs all resident.
// Slab of strip s touches strips s-2..s+2 (same image) only; cross-image
// reads feed only discarded (non-interior) outputs. So per-step sync is a
// 5-flag neighbor wait, not a device-wide barrier; max neighbor skew = 1 step,
// hence the 2-buffer h ping-pong remains sufficient.
#define SM_WP    66560
#define SM_BP    74752
#define SM_C     75008
#define SM_TOTAL 91392

__global__ void __launch_bounds__(256, 2)
step_all_kernel(const float* __restrict__ Wp, const float* __restrict__ bp,
                const float* __restrict__ xin, float* __restrict__ out)
{
    extern __shared__ __align__(16) char smem[];
    float* zs   = (float*)smem;
    float* wp_s = (float*)(smem + SM_WP);
    float* bp_s = (float*)(smem + SM_BP);
    float* c_s  = (float*)(smem + SM_C);

    const int tid  = threadIdx.x;
    const int lane = tid & 31;
    const int wn   = tid >> 5;      // 0..7
    const int b    = blockIdx.y;
    const int strip = blockIdx.x;
    const int q0   = strip * 64;

    for (int i = tid; i < 2048; i += 256) wp_s[i] = Wp[i];
    if (tid < 64) bp_s[tid] = bp[tid];
    for (int i = tid; i < 4096; i += 256) c_s[i] = 0.f;

    const uint32_t sh_u = smem_u32(smem);
    const int rowA = lane & 15;
    const int colh = (lane >> 4) * 16;
    const uint2* pbase = g_WhF + wn * 128 + lane;

    // neighbor flag pointer for lanes 0..4 (strips strip-2..strip+2, clamped)
    const unsigned* my_flagp = 0;
    if (tid < 5) {
        int ns = strip + tid - 2;
        if (ns < 0) ns = 0;
        if (ns > NSTRIP - 1) ns = NSTRIP - 1;
        my_flagp = &g_flag[b * NSTRIP + ns];
    }

    // epilogue constants
    const int pxl = tid >> 2;          // 0..63
    const int q   = q0 + pxl;
    const int py  = q / 66, pxc = q % 66;
    const bool inter = (q < PPX) && py >= 1 && py <= 64 && pxc >= 1 && pxc <= 64;
    const int f0base = (tid & 3) * 16;

    for (int t = 0; t < TT; ++t) {
        const int bt = b * TT + t;

        // ---- wait for neighbor strips to finish step t-1 ----
        if (t > 0) {
            if (tid < 5) {
                while (ld_vol(my_flagp) < (unsigned)t) { __nanosleep(32); }
            }
            __syncthreads();
            __threadfence();   // acquire: order slab reads after flag observation
        }

        // ---- load h slab (L2-only: L1 not coherent across SMs) ----
        {
            long off = (long)GRD * 64 + ((long)b * PPX + q0 - 67) * 64;
            const uint4* sh = (const uint4*)(g_h[t & 1] + off);
            for (int i = tid; i < 1584; i += 256) {
                int r = i >> 3, c = i & 7;
                *(uint4*)(smem + r * 144 + c * 16) = ldcg4(sh + i);
            }
        }
        __syncthreads();

        float acc[4][4][4];
#pragma unroll
        for (int mt = 0; mt < 4; ++mt)
#pragma unroll
            for (int nt = 0; nt < 4; ++nt)
#pragma unroll
                for (int e = 0; e < 4; ++e) acc[mt][nt][e] = 0.f;

        uint2 bcur[4], bnxt[4];
#pragma unroll
        for (int nt = 0; nt < 4; ++nt) bcur[nt] = pbase[nt * 32];

        // ---- h taps: 36 (tap,chunk) pairs, B prefetch double-buffered ----
#pragma unroll 2
        for (int tc = 0; tc < 36; ++tc) {
            const uint2* pn = pbase + (size_t)(tc + 1 < 36 ? tc + 1 : 35) * 1024;
#pragma unroll
            for (int nt = 0; nt < 4; ++nt) bnxt[nt] = pn[nt * 32];

            const int tap = tc >> 2, chunk = tc & 3;
            const int shift = (tap / 3) * 66 + (tap % 3);
            const uint32_t a_base = sh_u + (uint32_t)(shift + rowA) * 144 + colh + chunk * 32;
#pragma unroll
            for (int mt = 0; mt < 4; ++mt) {
                uint32_t ah[4];
                LDMX4(ah, a_base + mt * (16 * 144));
#pragma unroll
                for (int nt = 0; nt < 4; ++nt) MMA_FP16(acc[mt][nt], ah, bcur[nt]);
            }
#pragma unroll
            for (int nt = 0; nt < 4; ++nt) bcur[nt] = bnxt[nt];
        }

        __syncthreads();   // done reading slab; z aliases it

        // ---- scatter z to smem ----
#pragma unroll
        for (int mt = 0; mt < 4; ++mt)
#pragma unroll
            for (int nt = 0; nt < 4; ++nt) {
                int px = mt * 16 + (lane >> 2);
                int n  = wn * 32 + nt * 8 + (lane & 3) * 2;
                *(float2*)(zs + px * 260 + n)       = make_float2(acc[mt][nt][0], acc[mt][nt][1]);
                *(float2*)(zs + (px + 8) * 260 + n) = make_float2(acc[mt][nt][2], acc[mt][nt][3]);
            }
        __syncthreads();

        // ---- epilogue ----
        if (inter) {
            unsigned short* ho = (unsigned short*)(g_h[(t + 1) & 1] + GRD * 64 + ((size_t)b * PPX + q) * 64);
            float* op = out + ((size_t)bt * 4096 + (py - 1) * 64 + (pxc - 1)) * 64;
            const float* zrow  = zs + pxl * 260;
            const __half* zxrow = g_zx + (((size_t)bt * NSTRIP + strip) * 64 + pxl) * 256;
            const float* xrow  = xin + ((size_t)bt * 4096 + (py - 1) * 64 + (pxc - 1)) * 32;
            float* crow = c_s + pxl * 64;

            float4 xr[8];
#pragma unroll
            for (int i = 0; i < 8; ++i) xr[i] = __ldg((const float4*)xrow + i);

#pragma unroll
            for (int j4 = 0; j4 < 4; ++j4) {
                int f0 = f0base + j4 * 4;
                float4 res = *(const float4*)(bp_s + f0);
#pragma unroll
                for (int ci4 = 0; ci4 < 8; ++ci4) {
                    const float* xv = &xr[ci4].x;
#pragma unroll
                    for (int cc = 0; cc < 4; ++cc) {
                        float4 w = *(const float4*)(wp_s + (ci4 * 4 + cc) * 64 + f0);
                        float xs = xv[cc];
                        res.x = fmaf(xs, w.x, res.x);
                        res.y = fmaf(xs, w.y, res.y);
                        res.z = fmaf(xs, w.z, res.z);
                        res.w = fmaf(xs, w.w, res.w);
                    }
                }

                float4 zi = *(const float4*)(zrow + f0);
                float4 zf = *(const float4*)(zrow + 64 + f0);
                float4 zc = *(const float4*)(zrow + 128 + f0);
                float4 zo = *(const float4*)(zrow + 192 + f0);

                uint2 uxi = __ldg((const uint2*)(zxrow + f0));
                uint2 uxf = __ldg((const uint2*)(zxrow + 64 + f0));
                uint2 uxc = __ldg((const uint2*)(zxrow + 128 + f0));
                uint2 uxo = __ldg((const uint2*)(zxrow + 192 + f0));
                float2 xi0 = __half22float2(*(__half2*)&uxi.x), xi1 = __half22float2(*(__half2*)&uxi.y);
                float2 xf0 = __half22float2(*(__half2*)&uxf.x), xf1 = __half22float2(*(__half2*)&uxf.y);
                float2 xc0 = __half22float2(*(__half2*)&uxc.x), xc1 = __half22float2(*(__half2*)&uxc.y);
                float2 xo0 = __half22float2(*(__half2*)&uxo.x), xo1 = __half22float2(*(__half2*)&uxo.y);
                float xiv[4] = {xi0.x, xi0.y, xi1.x, xi1.y};
                float xfv[4] = {xf0.x, xf0.y, xf1.x, xf1.y};
                float xcv[4] = {xc0.x, xc0.y, xc1.x, xc1.y};
                float xov[4] = {xo0.x, xo0.y, xo1.x, xo1.y};

                float4 c4 = *(float4*)(crow + f0);
                float4 o4;
                unsigned short hh[4];
#pragma unroll
                for (int e = 0; e < 4; ++e) {
                    float vi = (&zi.x)[e] + xiv[e];
                    float vf = (&zf.x)[e] + xfv[e];
                    float vc = (&zc.x)[e] + xcv[e];
                    float vo = (&zo.x)[e] + xov[e];
                    float ig = __saturatef(fmaf(0.2f, vi, 0.5f));
                    float fg = __saturatef(fmaf(0.2f, vf, 0.5f));
                    float og = __saturatef(fmaf(0.2f, vo, 0.5f));
                    float cn = fmaf(fg, (&c4.x)[e], ig * tanhf(vc));
                    (&c4.x)[e] = cn;
                    float hv = og * tanhf(cn);
                    (&o4.x)[e] = hv + (&res.x)[e];
                    hh[e] = __half_as_ushort(__float2half_rn(hv));
                }
                *(float4*)(crow + f0) = c4;
                *(float4*)(op + f0)   = o4;
                uint2 phv = make_uint2((uint32_t)hh[0] | ((uint32_t)hh[1] << 16),
                                       (uint32_t)hh[2] | ((uint32_t)hh[3] << 16));
                *(uint2*)(ho + f0) = phv;
            }
        }

        // ---- publish h[t+1] for this strip ----
        __syncthreads();
        __threadfence();
        if (tid == 0) atomicExch(&g_flag[b * NSTRIP + strip], (unsigned)(t + 1));
    }
}

// ---------------------------------------------------------------------------
extern "C" void kernel_launch(void* const* d_in, const int* in_sizes, int n_in,
                              void* d_out, int out_size)
{
    const float* x  = (const float*)d_in[0];
    const float* Wx = (const float*)d_in[1];
    const float* Wh = (const float*)d_in[2];
    const float* b  = (const float*)d_in[3];
    const float* Wp = (const float*)d_in[4];
    const float* bp = (const float*)d_in[5];
    float* out = (float*)d_out;

    cudaFuncSetAttribute(step_all_kernel,
                         cudaFuncAttributeMaxDynamicSharedMemorySize, SM_TOTAL);
    cudaFuncSetAttribute(xconv_kernel,
                         cudaFuncAttributeMaxDynamicSharedMemorySize, XC_SMEM);

    zero_kernel<<<(NTOT + 255) / 256, 256>>>();
    pad_x_kernel<<<(int)((XTOT + 255) / 256), 256>>>(x);
    prep_w_kernel<<<(36864 + 18432 + 255) / 256, 256>>>(Wx, Wh);

    dim3 xgrid(NSTRIP, BBATCH * TT);
    xconv_kernel<<<xgrid, 256, XC_SMEM>>>(b);

    dim3 grid(NSTRIP, BBATCH);
    step_all_kernel<<<grid, 256, SM_TOTAL>>>(Wp, bp, x, out);
}